// round 12
// baseline (speedup 1.0000x reference)
#include <cuda_runtime.h>
#include <cstdint>
#include <math.h>

#define N_SEQ     16384
#define TBL_N     1024             // intervals; TBL_N+1 knots
#define CHUNK     4096             // elements per map block
#define NTB       65               // table blocks: bids 1..NTB, 16 knots each
#define S_THREADS 512

// -------------------------- device scratch ---------------------------------
__device__ __align__(8)  float2 g_tbl2[TBL_N];    // (f[i], f[i+1]) pairs
__device__ __align__(16) float4 g_coef[TBL_N];    // (G_i, a_i, b_i, 0)
__device__ float2 g_range;                        // (lo, inv_h)
__device__ float  g_h;                            // knot spacing
// packed weights: pW[k4 * NROWS + row] = float4 of W[row][4*k4 .. 4*k4+3]
__device__ __align__(16) float4 g_pW2[8  * 64];
__device__ __align__(16) float4 g_pW3[16 * 64];
__device__ __align__(16) float4 g_pW4[16 * 32];
// pipeline flags (reset by last block each run -> graph-replay safe)
__device__ volatile int g_flag1;    // range + packed weights ready
__device__ volatile int g_flag2;    // coef table ready
__device__ int g_cnt1;              // table blocks completed
__device__ int g_done;              // blocks finished (for reset)

// -------------------------- math helpers -----------------------------------
__device__ __forceinline__ float splus(float x) {
    float e = __expf(-fabsf(x));
    return fmaxf(x, 0.0f) + __logf(1.0f + e);
}

__device__ __forceinline__ float evalG(float tv, float lo, float inv_h) {
    float u = (tv - lo) * inv_h;
    u = fminf(fmaxf(u, 0.0f), (float)TBL_N);
    int i = (int)u;
    if (i > TBL_N - 1) i = TBL_N - 1;
    float frac = u - (float)i;
    float4 c = __ldg(&g_coef[i]);
    return fmaf(frac, fmaf(frac, c.z, c.y), c.x);
}

// ----------------------------- the one kernel -------------------------------
__global__ __launch_bounds__(S_THREADS) void fused_kernel(
    const float* __restrict__ t, float* __restrict__ out,
    const float* __restrict__ W1, const float* __restrict__ b1,
    const float* __restrict__ W2, const float* __restrict__ b2,
    const float* __restrict__ W3, const float* __restrict__ b3,
    const float* __restrict__ W4, const float* __restrict__ b4,
    const float* __restrict__ W5, const float* __restrict__ b5,
    int nrows, int nblocks)
{
    __shared__ __align__(16) float hbuf[16][2][64];   // table: per-warp hidden
    __shared__ float s_a[16], s_b[16];                // reductions / scan
    const unsigned m = 0xffffffffu;

    int bid = blockIdx.x;
    int tid = threadIdx.x;
    int wid = tid >> 5, lane = tid & 31;

    int row = bid >> 2;                                // NCHUNK = 4
    size_t base = (size_t)row * N_SEQ + (size_t)(bid & 3) * CHUNK;
    const float4* t4 = reinterpret_cast<const float4*>(t + base);

    // plain map blocks: prefetch chunk NOW (overlaps table phase)
    float4 cur0, cur1;
    if (bid > NTB) {
        cur0 = t4[tid];
        cur1 = t4[tid + S_THREADS];
    }

    if (bid == 0) {
        // ---------- pack weights float4-transposed (coalesced for table) ----
        const float4* W2v = reinterpret_cast<const float4*>(W2);
        const float4* W3v = reinterpret_cast<const float4*>(W3);
        const float4* W4v = reinterpret_cast<const float4*>(W4);
        for (int i = tid; i < 512; i += S_THREADS) {   // W2 [64 rows][8 f4]
            int k4 = i >> 6, j = i & 63;
            g_pW2[i] = W2v[j * 8 + k4];
        }
        for (int i = tid; i < 1024; i += S_THREADS) {  // W3 [64 rows][16 f4]
            int k4 = i >> 6, j = i & 63;
            g_pW3[i] = W3v[j * 16 + k4];
        }
        for (int i = tid; i < 512; i += S_THREADS) {   // W4 [32 rows][16 f4]
            int k4 = i >> 5, j = i & 31;
            g_pW4[i] = W4v[j * 16 + k4];
        }
        // ---------- edge range (t sorted per row) ---------------------------
        float l = 3.4e38f, h = -3.4e38f;
        for (int r = tid; r < nrows; r += S_THREADS) {
            l = fminf(l, t[(size_t)r * N_SEQ]);
            h = fmaxf(h, t[(size_t)r * N_SEQ + (N_SEQ - 1)]);
        }
#pragma unroll
        for (int off = 16; off > 0; off >>= 1) {
            l = fminf(l, __shfl_down_sync(m, l, off));
            h = fmaxf(h, __shfl_down_sync(m, h, off));
        }
        if (lane == 0) { s_a[wid] = l; s_b[wid] = h; }
        __syncthreads();
        if (tid == 0) {
            float lo = s_a[0], hi = s_b[0];
#pragma unroll
            for (int w = 1; w < 16; w++) {
                lo = fminf(lo, s_a[w]); hi = fmaxf(hi, s_b[w]);
            }
            float range = hi - lo;
            g_h = (range > 1e-30f) ? range * (1.0f / TBL_N) : 1.0f;
            g_range = make_float2(lo,
                (range > 1e-30f) ? (float)TBL_N / range : 0.0f);
            __threadfence();
            g_flag1 = 1;                                  // release
        }
        // ---------- wait for table, then prefix -> coefficients -------------
        if (tid == 0) {
            while (*(volatile int*)&g_cnt1 != NTB) __nanosleep(64);
            __threadfence();                              // acquire
        }
        __syncthreads();
        {
            float hh = g_h;
            int i0 = 2 * tid, i1 = 2 * tid + 1;
            float2 f0 = g_tbl2[i0];
            float2 f1 = g_tbl2[i1];
            float a0 = hh * f0.x, b0 = 0.5f * hh * (f0.y - f0.x);
            float a1 = hh * f1.x, b1c = 0.5f * hh * (f1.y - f1.x);
            float s0 = a0 + b0, s1 = a1 + b1c;
            float tot = s0 + s1;
            float v = tot;
#pragma unroll
            for (int off = 1; off < 32; off <<= 1) {
                float n = __shfl_up_sync(m, v, off);
                if (lane >= off) v += n;
            }
            if (lane == 31) s_a[wid] = v;
            __syncthreads();
            if (wid == 0) {
                float w = (lane < 16) ? s_a[lane] : 0.0f;
#pragma unroll
                for (int off = 1; off < 16; off <<= 1) {
                    float n = __shfl_up_sync(m, w, off);
                    if (lane >= off) w += n;
                }
                if (lane < 16) s_a[lane] = w;
            }
            __syncthreads();
            float excl = ((wid > 0) ? s_a[wid - 1] : 0.0f) + (v - tot);
            g_coef[i0] = make_float4(excl,      a0, b0,  0.0f);
            g_coef[i1] = make_float4(excl + s0, a1, b1c, 0.0f);
        }
        __syncthreads();
        if (tid == 0) { __threadfence(); g_flag2 = 1; }   // release
    }
    else if (bid <= NTB) {
        // ---------- table: 16 warps, one knot each ---------------------------
        if (tid == 0) {
            while (g_flag1 == 0) __nanosleep(64);
            __threadfence();                              // acquire
        }
        __syncthreads();
        int kn = (bid - 1) * 16 + wid;
        if (kn <= TBL_N) {
            float2 rg = g_range;
            float tv = rg.x + (float)kn * g_h;

            // layer 1: 1 -> 32
            hbuf[wid][0][lane] =
                splus(fmaf(tv, __ldg(&W1[lane]), __ldg(&b1[lane])));
            __syncwarp();
            // layer 2: 32 -> 64
            {
                const float4* hv4 = reinterpret_cast<const float4*>(hbuf[wid][0]);
                float a0 = __ldg(&b2[lane]), a1 = __ldg(&b2[lane + 32]);
#pragma unroll
                for (int k4 = 0; k4 < 8; k4++) {
                    float4 hv = hv4[k4];
                    float4 w0 = __ldg(&g_pW2[k4 * 64 + lane]);
                    float4 w1 = __ldg(&g_pW2[k4 * 64 + 32 + lane]);
                    a0 = fmaf(w0.x, hv.x, a0); a0 = fmaf(w0.y, hv.y, a0);
                    a0 = fmaf(w0.z, hv.z, a0); a0 = fmaf(w0.w, hv.w, a0);
                    a1 = fmaf(w1.x, hv.x, a1); a1 = fmaf(w1.y, hv.y, a1);
                    a1 = fmaf(w1.z, hv.z, a1); a1 = fmaf(w1.w, hv.w, a1);
                }
                hbuf[wid][1][lane]      = splus(a0);
                hbuf[wid][1][lane + 32] = splus(a1);
            }
            __syncwarp();
            // layer 3: 64 -> 64
            {
                const float4* hv4 = reinterpret_cast<const float4*>(hbuf[wid][1]);
                float a0 = __ldg(&b3[lane]), a1 = __ldg(&b3[lane + 32]);
#pragma unroll
                for (int k4 = 0; k4 < 16; k4++) {
                    float4 hv = hv4[k4];
                    float4 w0 = __ldg(&g_pW3[k4 * 64 + lane]);
                    float4 w1 = __ldg(&g_pW3[k4 * 64 + 32 + lane]);
                    a0 = fmaf(w0.x, hv.x, a0); a0 = fmaf(w0.y, hv.y, a0);
                    a0 = fmaf(w0.z, hv.z, a0); a0 = fmaf(w0.w, hv.w, a0);
                    a1 = fmaf(w1.x, hv.x, a1); a1 = fmaf(w1.y, hv.y, a1);
                    a1 = fmaf(w1.z, hv.z, a1); a1 = fmaf(w1.w, hv.w, a1);
                }
                hbuf[wid][0][lane]      = splus(a0);
                hbuf[wid][0][lane + 32] = splus(a1);
            }
            __syncwarp();
            // layer 4: 64 -> 32
            float h4;
            {
                const float4* hv4 = reinterpret_cast<const float4*>(hbuf[wid][0]);
                float a0 = __ldg(&b4[lane]);
#pragma unroll
                for (int k4 = 0; k4 < 16; k4++) {
                    float4 hv = hv4[k4];
                    float4 w0 = __ldg(&g_pW4[k4 * 32 + lane]);
                    a0 = fmaf(w0.x, hv.x, a0); a0 = fmaf(w0.y, hv.y, a0);
                    a0 = fmaf(w0.z, hv.z, a0); a0 = fmaf(w0.w, hv.w, a0);
                }
                h4 = splus(a0);
            }
            // layer 5: 32 -> 1
            float p = h4 * __ldg(&W5[lane]);
#pragma unroll
            for (int off = 16; off > 0; off >>= 1)
                p += __shfl_xor_sync(m, p, off);
            if (lane == 0) {
                float v = splus(p + __ldg(&b5[0])) + 1.0f;
                float* tbl = reinterpret_cast<float*>(g_tbl2);
                if (kn < TBL_N) tbl[2 * kn] = v;
                if (kn >= 1)    tbl[2 * (kn - 1) + 1] = v;
            }
        }
        __syncthreads();
        if (tid == 0) { __threadfence(); atomicAdd(&g_cnt1, 1); }
    }

    // ---------------- all blocks: wait for coefficients, then map -----------
    if (tid == 0) {
        while (g_flag2 == 0) __nanosleep(64);
        __threadfence();                                  // acquire
    }
    __syncthreads();

    float2 rg = g_range;
    float lo = rg.x, inv_h = rg.y;
    if (bid <= NTB) {                 // special blocks load their chunk now
        cur0 = t4[tid];
        cur1 = t4[tid + S_THREADS];
    }
    float G0 = evalG(__ldg(&t[(size_t)row * N_SEQ]), lo, inv_h);

    float4* o4 = reinterpret_cast<float4*>(out + base);
    float4 o;
    o.x = evalG(cur0.x, lo, inv_h) - G0;
    o.y = evalG(cur0.y, lo, inv_h) - G0;
    o.z = evalG(cur0.z, lo, inv_h) - G0;
    o.w = evalG(cur0.w, lo, inv_h) - G0;
    o4[tid] = o;
    o.x = evalG(cur1.x, lo, inv_h) - G0;
    o.y = evalG(cur1.y, lo, inv_h) - G0;
    o.z = evalG(cur1.z, lo, inv_h) - G0;
    o.w = evalG(cur1.w, lo, inv_h) - G0;
    o4[tid + S_THREADS] = o;

    // ---------------- reset pipeline state for the next graph replay --------
    __syncthreads();
    if (tid == 0) {
        __threadfence();
        int old = atomicAdd(&g_done, 1);
        if (old == nblocks - 1) {     // last block: everyone passed the spins
            g_flag1 = 0;
            g_flag2 = 0;
            g_cnt1  = 0;
            g_done  = 0;
        }
    }
}

// ----------------------------------------------------------------------------
extern "C" void kernel_launch(void* const* d_in, const int* in_sizes, int n_in,
                              void* d_out, int out_size) {
    const float* t  = (const float*)d_in[0];
    const float* W1 = (const float*)d_in[1];
    const float* b1 = (const float*)d_in[2];
    const float* W2 = (const float*)d_in[3];
    const float* b2 = (const float*)d_in[4];
    const float* W3 = (const float*)d_in[5];
    const float* b3 = (const float*)d_in[6];
    const float* W4 = (const float*)d_in[7];
    const float* b4 = (const float*)d_in[8];
    const float* W5 = (const float*)d_in[9];
    const float* b5 = (const float*)d_in[10];
    float* out = (float*)d_out;

    int total = in_sizes[0];          // B * N
    int nrows = total / N_SEQ;        // B
    int nblocks = total / CHUNK;      // 1024

    fused_kernel<<<nblocks, S_THREADS>>>(t, out, W1, b1, W2, b2, W3, b3,
                                         W4, b4, W5, b5, nrows, nblocks);
}

// round 13
// speedup vs baseline: 1.2756x; 1.2756x over previous
#include <cuda_runtime.h>
#include <cstdint>
#include <math.h>

#define N_SEQ   16384
#define TBL_N   1024               // intervals; TBL_N+1 knots
#define CHUNK   4096               // elements per map block
#define NTB     65                 // table blocks (16 knots each, 1025 knots)

#define INP2 36                    // padded row widths (odd multiple of 16B)
#define INP3 68
#define INP4 68

// -------------------------- device scratch ---------------------------------
__device__ __align__(8)  float2 g_tbl2[TBL_N];    // (f[i], f[i+1]) pairs
__device__ __align__(16) float4 g_coef[TBL_N];    // (G_i, a_i, b_i, 0)
__device__ float2 g_range;                        // (lo, inv_h)
__device__ int    g_cnt;                          // table blocks done (self-reset)

// -------------------------- math helpers -----------------------------------
__device__ __forceinline__ float splus(float x) {
    float e = __expf(-fabsf(x));
    return fmaxf(x, 0.0f) + __logf(1.0f + e);
}

// ---------------- kernel 1: range + f at knots + prefix ---------------------
// 65 independent blocks. Each block: (a) redundantly reduces the row-edge
// range (t sorted per row -> min of heads / max of tails), (b) stages weights
// into padded smem, (c) 16 warps compute 16 knots, (d) the LAST block (atomic
// counter) computes the antiderivative coefficients. No inter-block waiting
// on the critical path except the tiny prefix tail.
__global__ __launch_bounds__(512) void table_kernel(
    const float* __restrict__ t, int nrows,
    const float* __restrict__ W1, const float* __restrict__ b1,
    const float* __restrict__ W2, const float* __restrict__ b2,
    const float* __restrict__ W3, const float* __restrict__ b3,
    const float* __restrict__ W4, const float* __restrict__ b4,
    const float* __restrict__ W5, const float* __restrict__ b5,
    int nblk)
{
    __shared__ __align__(16) float sW2p[64 * INP2];
    __shared__ __align__(16) float sW3p[64 * INP3];
    __shared__ __align__(16) float sW4p[32 * INP4];
    __shared__ __align__(16) float hbuf[16][2][64];   // [warp][pingpong][unit]
    __shared__ float sW1[32], sB1[32], sB2[64], sB3[64], sB4[32], sW5[32];
    __shared__ float sB5;
    __shared__ float s_a[16], s_b[16];
    __shared__ float s_lo, s_h;
    __shared__ int   s_last;

    int tid = threadIdx.x;
    int wid = tid >> 5, lane = tid & 31;
    const unsigned m = 0xffffffffu;

    // ---- stage weights (coalesced loads, padded rows for conflict-free LDS.128)
    for (int d = tid; d < 2048; d += 512) {        // W2 [64][32]
        int j = d >> 5, k = d & 31;
        sW2p[j * INP2 + k] = W2[d];
    }
    for (int d = tid; d < 4096; d += 512) {        // W3 [64][64]
        int j = d >> 6, k = d & 63;
        sW3p[j * INP3 + k] = W3[d];
    }
    for (int d = tid; d < 2048; d += 512) {        // W4 [32][64]
        int j = d >> 6, k = d & 63;
        sW4p[j * INP4 + k] = W4[d];
    }
    if (tid < 32) { sW1[tid] = W1[tid]; sB1[tid] = b1[tid];
                    sB4[tid] = b4[tid]; sW5[tid] = W5[tid]; }
    if (tid < 64) { sB2[tid] = b2[tid]; sB3[tid] = b3[tid]; }
    if (tid == 0) sB5 = b5[0];

    // ---- per-block redundant edge range (parallel with staging loads)
    float l = 3.4e38f, h = -3.4e38f;
    for (int r = tid; r < nrows; r += 512) {
        l = fminf(l, __ldg(&t[(size_t)r * N_SEQ]));
        h = fmaxf(h, __ldg(&t[(size_t)r * N_SEQ + (N_SEQ - 1)]));
    }
#pragma unroll
    for (int off = 16; off > 0; off >>= 1) {
        l = fminf(l, __shfl_down_sync(m, l, off));
        h = fmaxf(h, __shfl_down_sync(m, h, off));
    }
    if (lane == 0) { s_a[wid] = l; s_b[wid] = h; }
    __syncthreads();
    if (tid == 0) {
        float lo = s_a[0], hi = s_b[0];
#pragma unroll
        for (int w = 1; w < 16; w++) {
            lo = fminf(lo, s_a[w]); hi = fmaxf(hi, s_b[w]);
        }
        float range = hi - lo;
        float hh    = (range > 1e-30f) ? range * (1.0f / TBL_N) : 1.0f;
        float inv_h = (range > 1e-30f) ? (float)TBL_N / range : 0.0f;
        s_lo = lo; s_h = hh;
        if (blockIdx.x == 0) g_range = make_float2(lo, inv_h);
    }
    __syncthreads();

    // ---- MLP: warp wid computes knot kn
    int kn = blockIdx.x * 16 + wid;
    if (kn <= TBL_N) {
        float tv = s_lo + (float)kn * s_h;

        // layer 1: 1 -> 32
        hbuf[wid][0][lane] = splus(fmaf(tv, sW1[lane], sB1[lane]));
        __syncwarp();
        // layer 2: 32 -> 64
        {
            const float4* hv4 = reinterpret_cast<const float4*>(hbuf[wid][0]);
            const float4* w0r = reinterpret_cast<const float4*>(sW2p + lane * INP2);
            const float4* w1r = reinterpret_cast<const float4*>(sW2p + (lane + 32) * INP2);
            float a0 = sB2[lane], a1 = sB2[lane + 32];
#pragma unroll
            for (int k4 = 0; k4 < 8; k4++) {
                float4 hv = hv4[k4];
                float4 w0 = w0r[k4];
                float4 w1 = w1r[k4];
                a0 = fmaf(w0.x, hv.x, a0); a0 = fmaf(w0.y, hv.y, a0);
                a0 = fmaf(w0.z, hv.z, a0); a0 = fmaf(w0.w, hv.w, a0);
                a1 = fmaf(w1.x, hv.x, a1); a1 = fmaf(w1.y, hv.y, a1);
                a1 = fmaf(w1.z, hv.z, a1); a1 = fmaf(w1.w, hv.w, a1);
            }
            hbuf[wid][1][lane]      = splus(a0);
            hbuf[wid][1][lane + 32] = splus(a1);
        }
        __syncwarp();
        // layer 3: 64 -> 64
        {
            const float4* hv4 = reinterpret_cast<const float4*>(hbuf[wid][1]);
            const float4* w0r = reinterpret_cast<const float4*>(sW3p + lane * INP3);
            const float4* w1r = reinterpret_cast<const float4*>(sW3p + (lane + 32) * INP3);
            float a0 = sB3[lane], a1 = sB3[lane + 32];
#pragma unroll
            for (int k4 = 0; k4 < 16; k4++) {
                float4 hv = hv4[k4];
                float4 w0 = w0r[k4];
                float4 w1 = w1r[k4];
                a0 = fmaf(w0.x, hv.x, a0); a0 = fmaf(w0.y, hv.y, a0);
                a0 = fmaf(w0.z, hv.z, a0); a0 = fmaf(w0.w, hv.w, a0);
                a1 = fmaf(w1.x, hv.x, a1); a1 = fmaf(w1.y, hv.y, a1);
                a1 = fmaf(w1.z, hv.z, a1); a1 = fmaf(w1.w, hv.w, a1);
            }
            hbuf[wid][0][lane]      = splus(a0);
            hbuf[wid][0][lane + 32] = splus(a1);
        }
        __syncwarp();
        // layer 4: 64 -> 32
        float h4;
        {
            const float4* hv4 = reinterpret_cast<const float4*>(hbuf[wid][0]);
            const float4* w0r = reinterpret_cast<const float4*>(sW4p + lane * INP4);
            float a0 = sB4[lane];
#pragma unroll
            for (int k4 = 0; k4 < 16; k4++) {
                float4 hv = hv4[k4];
                float4 w0 = w0r[k4];
                a0 = fmaf(w0.x, hv.x, a0); a0 = fmaf(w0.y, hv.y, a0);
                a0 = fmaf(w0.z, hv.z, a0); a0 = fmaf(w0.w, hv.w, a0);
            }
            h4 = splus(a0);
        }
        // layer 5: 32 -> 1 (warp reduce)
        float p = h4 * sW5[lane];
#pragma unroll
        for (int off = 16; off > 0; off >>= 1)
            p += __shfl_xor_sync(m, p, off);

        if (lane == 0) {
            float v = splus(p + sB5) + 1.0f;
            float* tbl = reinterpret_cast<float*>(g_tbl2);
            // slot kn: (f[kn], f[kn+1]); warp kn fills .x of kn, .y of kn-1.
            if (kn < TBL_N) tbl[2 * kn] = v;
            if (kn >= 1)    tbl[2 * (kn - 1) + 1] = v;
            __threadfence();                 // publish before the counter
        }
    }
    __syncthreads();

    // ---- last block computes the antiderivative coefficients ----
    if (tid == 0) {
        int old = atomicAdd(&g_cnt, 1);
        s_last = (old == nblk - 1);
    }
    __syncthreads();
    if (!s_last) return;

    {
        float hh = s_h;
        int i0 = 2 * tid, i1 = 2 * tid + 1;
        float2 f0 = __ldcg(&g_tbl2[i0]);     // L2 reads (skip stale L1)
        float2 f1 = __ldcg(&g_tbl2[i1]);
        float a0 = hh * f0.x, b0  = 0.5f * hh * (f0.y - f0.x);
        float a1 = hh * f1.x, b1c = 0.5f * hh * (f1.y - f1.x);
        float s0 = a0 + b0, s1 = a1 + b1c;
        float tot = s0 + s1;

        float v = tot;
#pragma unroll
        for (int off = 1; off < 32; off <<= 1) {
            float n = __shfl_up_sync(m, v, off);
            if (lane >= off) v += n;
        }
        if (lane == 31) s_a[wid] = v;
        __syncthreads();
        if (wid == 0) {
            float w = (lane < 16) ? s_a[lane] : 0.0f;
#pragma unroll
            for (int off = 1; off < 16; off <<= 1) {
                float n = __shfl_up_sync(m, w, off);
                if (lane >= off) w += n;
            }
            if (lane < 16) s_a[lane] = w;
        }
        __syncthreads();

        float excl = ((wid > 0) ? s_a[wid - 1] : 0.0f) + (v - tot);
        g_coef[i0] = make_float4(excl,      a0, b0,  0.0f);
        g_coef[i1] = make_float4(excl + s0, a1, b1c, 0.0f);
    }
    __syncthreads();
    if (tid == 0) g_cnt = 0;                 // reset for next graph replay
}

// -------------------------- kernel 2: pure map ------------------------------
#define S_THREADS 512
#define V4PT      (CHUNK / 4 / S_THREADS)  // 2 float4 per thread

__device__ __forceinline__ float evalG(float tv, float lo, float inv_h) {
    float u = (tv - lo) * inv_h;
    u = fminf(fmaxf(u, 0.0f), (float)TBL_N);
    int i = (int)u;
    if (i > TBL_N - 1) i = TBL_N - 1;
    float frac = u - (float)i;
    float4 c = __ldg(&g_coef[i]);
    return fmaf(frac, fmaf(frac, c.z, c.y), c.x);
}

__global__ __launch_bounds__(S_THREADS) void map_kernel(
    const float* __restrict__ t, float* __restrict__ out)
{
    int gid = blockIdx.x;
    int row = gid >> 2;                       // NCHUNK = 4
    size_t base = (size_t)row * N_SEQ + (size_t)(gid & 3) * CHUNK;

    float2 rg = g_range;
    float lo = rg.x, inv_h = rg.y;

    // row anchor
    float G0 = evalG(__ldg(&t[(size_t)row * N_SEQ]), lo, inv_h);

    const float4* t4 = reinterpret_cast<const float4*>(t + base);
    float4* o4 = reinterpret_cast<float4*>(out + base);
    int tid = threadIdx.x;
#pragma unroll
    for (int w = 0; w < V4PT; w++) {
        int idx = tid + w * S_THREADS;
        float4 v = t4[idx];
        float4 o;
        o.x = evalG(v.x, lo, inv_h) - G0;
        o.y = evalG(v.y, lo, inv_h) - G0;
        o.z = evalG(v.z, lo, inv_h) - G0;
        o.w = evalG(v.w, lo, inv_h) - G0;
        o4[idx] = o;
    }
}

// ----------------------------------------------------------------------------
extern "C" void kernel_launch(void* const* d_in, const int* in_sizes, int n_in,
                              void* d_out, int out_size) {
    const float* t  = (const float*)d_in[0];
    const float* W1 = (const float*)d_in[1];
    const float* b1 = (const float*)d_in[2];
    const float* W2 = (const float*)d_in[3];
    const float* b2 = (const float*)d_in[4];
    const float* W3 = (const float*)d_in[5];
    const float* b3 = (const float*)d_in[6];
    const float* W4 = (const float*)d_in[7];
    const float* b4 = (const float*)d_in[8];
    const float* W5 = (const float*)d_in[9];
    const float* b5 = (const float*)d_in[10];
    float* out = (float*)d_out;

    int total = in_sizes[0];          // B * N
    int nrows = total / N_SEQ;        // B

    table_kernel<<<NTB, 512>>>(t, nrows, W1, b1, W2, b2, W3, b3,
                               W4, b4, W5, b5, NTB);
    map_kernel<<<total / CHUNK, S_THREADS>>>(t, out);
}

// round 14
// speedup vs baseline: 1.2775x; 1.0015x over previous
#include <cuda_runtime.h>
#include <cstdint>
#include <math.h>

#define N_SEQ   16384
#define TBL_N   512                // intervals; TBL_N+1 knots
#define CHUNK   4096               // elements per map block
#define NTB     33                 // table blocks (16 knots each, 513 knots)

#define INP2 36                    // padded row widths (odd multiple of 16B)
#define INP3 68
#define INP4 68

// -------------------------- device scratch ---------------------------------
__device__ __align__(8)  float2 g_tbl2[TBL_N];      // (f[i], f[i+1]) pairs
__device__ __align__(16) float4 g_coef[TBL_N + 1];  // (G_i, a_i, b_i, 0) + pad
__device__ float2 g_range;                          // (lo, inv_h)
__device__ int    g_cnt;                            // table blocks done

// -------------------------- math helpers -----------------------------------
__device__ __forceinline__ float splus(float x) {
    float e = __expf(-fabsf(x));
    return fmaxf(x, 0.0f) + __logf(1.0f + e);
}

// ---------------- kernel 1: range + f at knots + prefix ---------------------
__global__ __launch_bounds__(512) void table_kernel(
    const float* __restrict__ t, int nrows,
    const float* __restrict__ W1, const float* __restrict__ b1,
    const float* __restrict__ W2, const float* __restrict__ b2,
    const float* __restrict__ W3, const float* __restrict__ b3,
    const float* __restrict__ W4, const float* __restrict__ b4,
    const float* __restrict__ W5, const float* __restrict__ b5,
    int nblk)
{
    __shared__ __align__(16) float sW2p[64 * INP2];
    __shared__ __align__(16) float sW3p[64 * INP3];
    __shared__ __align__(16) float sW4p[32 * INP4];
    __shared__ __align__(16) float hbuf[16][2][64];   // [warp][pingpong][unit]
    __shared__ float sW1[32], sB1[32], sB2[64], sB3[64], sB4[32], sW5[32];
    __shared__ float sB5;
    __shared__ float s_a[16], s_b[16];
    __shared__ float s_lo, s_h;
    __shared__ int   s_last;

    int tid = threadIdx.x;
    int wid = tid >> 5, lane = tid & 31;
    const unsigned m = 0xffffffffu;

    // ---- stage weights (coalesced; padded rows -> conflict-free LDS.128)
    for (int d = tid; d < 2048; d += 512) {        // W2 [64][32]
        int j = d >> 5, k = d & 31;
        sW2p[j * INP2 + k] = W2[d];
    }
    for (int d = tid; d < 4096; d += 512) {        // W3 [64][64]
        int j = d >> 6, k = d & 63;
        sW3p[j * INP3 + k] = W3[d];
    }
    for (int d = tid; d < 2048; d += 512) {        // W4 [32][64]
        int j = d >> 6, k = d & 63;
        sW4p[j * INP4 + k] = W4[d];
    }
    if (tid < 32) { sW1[tid] = W1[tid]; sB1[tid] = b1[tid];
                    sB4[tid] = b4[tid]; sW5[tid] = W5[tid]; }
    if (tid < 64) { sB2[tid] = b2[tid]; sB3[tid] = b3[tid]; }
    if (tid == 0) sB5 = b5[0];

    // ---- per-block redundant edge range (t sorted per row)
    float l = 3.4e38f, h = -3.4e38f;
    for (int r = tid; r < nrows; r += 512) {
        l = fminf(l, __ldg(&t[(size_t)r * N_SEQ]));
        h = fmaxf(h, __ldg(&t[(size_t)r * N_SEQ + (N_SEQ - 1)]));
    }
#pragma unroll
    for (int off = 16; off > 0; off >>= 1) {
        l = fminf(l, __shfl_down_sync(m, l, off));
        h = fmaxf(h, __shfl_down_sync(m, h, off));
    }
    if (lane == 0) { s_a[wid] = l; s_b[wid] = h; }
    __syncthreads();
    if (tid == 0) {
        float lo = s_a[0], hi = s_b[0];
#pragma unroll
        for (int w = 1; w < 16; w++) {
            lo = fminf(lo, s_a[w]); hi = fmaxf(hi, s_b[w]);
        }
        float range = hi - lo;
        float hh    = (range > 1e-30f) ? range * (1.0f / TBL_N) : 1.0f;
        float inv_h = (range > 1e-30f) ? (float)TBL_N / range : 0.0f;
        s_lo = lo; s_h = hh;
        if (blockIdx.x == 0) g_range = make_float2(lo, inv_h);
    }
    __syncthreads();

    // ---- MLP: warp wid computes knot kn
    int kn = blockIdx.x * 16 + wid;
    if (kn <= TBL_N) {
        float tv = s_lo + (float)kn * s_h;

        // layer 1: 1 -> 32
        hbuf[wid][0][lane] = splus(fmaf(tv, sW1[lane], sB1[lane]));
        __syncwarp();
        // layer 2: 32 -> 64
        {
            const float4* hv4 = reinterpret_cast<const float4*>(hbuf[wid][0]);
            const float4* w0r = reinterpret_cast<const float4*>(sW2p + lane * INP2);
            const float4* w1r = reinterpret_cast<const float4*>(sW2p + (lane + 32) * INP2);
            float a0 = sB2[lane], a1 = sB2[lane + 32];
#pragma unroll
            for (int k4 = 0; k4 < 8; k4++) {
                float4 hv = hv4[k4];
                float4 w0 = w0r[k4];
                float4 w1 = w1r[k4];
                a0 = fmaf(w0.x, hv.x, a0); a0 = fmaf(w0.y, hv.y, a0);
                a0 = fmaf(w0.z, hv.z, a0); a0 = fmaf(w0.w, hv.w, a0);
                a1 = fmaf(w1.x, hv.x, a1); a1 = fmaf(w1.y, hv.y, a1);
                a1 = fmaf(w1.z, hv.z, a1); a1 = fmaf(w1.w, hv.w, a1);
            }
            hbuf[wid][1][lane]      = splus(a0);
            hbuf[wid][1][lane + 32] = splus(a1);
        }
        __syncwarp();
        // layer 3: 64 -> 64
        {
            const float4* hv4 = reinterpret_cast<const float4*>(hbuf[wid][1]);
            const float4* w0r = reinterpret_cast<const float4*>(sW3p + lane * INP3);
            const float4* w1r = reinterpret_cast<const float4*>(sW3p + (lane + 32) * INP3);
            float a0 = sB3[lane], a1 = sB3[lane + 32];
#pragma unroll
            for (int k4 = 0; k4 < 16; k4++) {
                float4 hv = hv4[k4];
                float4 w0 = w0r[k4];
                float4 w1 = w1r[k4];
                a0 = fmaf(w0.x, hv.x, a0); a0 = fmaf(w0.y, hv.y, a0);
                a0 = fmaf(w0.z, hv.z, a0); a0 = fmaf(w0.w, hv.w, a0);
                a1 = fmaf(w1.x, hv.x, a1); a1 = fmaf(w1.y, hv.y, a1);
                a1 = fmaf(w1.z, hv.z, a1); a1 = fmaf(w1.w, hv.w, a1);
            }
            hbuf[wid][0][lane]      = splus(a0);
            hbuf[wid][0][lane + 32] = splus(a1);
        }
        __syncwarp();
        // layer 4: 64 -> 32
        float h4;
        {
            const float4* hv4 = reinterpret_cast<const float4*>(hbuf[wid][0]);
            const float4* w0r = reinterpret_cast<const float4*>(sW4p + lane * INP4);
            float a0 = sB4[lane];
#pragma unroll
            for (int k4 = 0; k4 < 16; k4++) {
                float4 hv = hv4[k4];
                float4 w0 = w0r[k4];
                a0 = fmaf(w0.x, hv.x, a0); a0 = fmaf(w0.y, hv.y, a0);
                a0 = fmaf(w0.z, hv.z, a0); a0 = fmaf(w0.w, hv.w, a0);
            }
            h4 = splus(a0);
        }
        // layer 5: 32 -> 1 (warp reduce)
        float p = h4 * sW5[lane];
#pragma unroll
        for (int off = 16; off > 0; off >>= 1)
            p += __shfl_xor_sync(m, p, off);

        if (lane == 0) {
            float v = splus(p + sB5) + 1.0f;
            float* tbl = reinterpret_cast<float*>(g_tbl2);
            if (kn < TBL_N) tbl[2 * kn] = v;
            if (kn >= 1)    tbl[2 * (kn - 1) + 1] = v;
            __threadfence();                 // publish before the counter
        }
    }
    __syncthreads();

    // ---- last block computes antiderivative coefficients -------------------
    if (tid == 0) {
        int old = atomicAdd(&g_cnt, 1);
        s_last = (old == nblk - 1);
    }
    __syncthreads();
    if (!s_last) return;

    {
        float hh = s_h;
        // one interval per thread (TBL_N = 512)
        float2 f0 = __ldcg(&g_tbl2[tid]);
        float a0 = hh * f0.x, b0 = 0.5f * hh * (f0.y - f0.x);
        float s0 = a0 + b0;

        float v = s0;
#pragma unroll
        for (int off = 1; off < 32; off <<= 1) {
            float n = __shfl_up_sync(m, v, off);
            if (lane >= off) v += n;
        }
        if (lane == 31) s_a[wid] = v;
        __syncthreads();
        if (wid == 0) {
            float w = (lane < 16) ? s_a[lane] : 0.0f;
#pragma unroll
            for (int off = 1; off < 16; off <<= 1) {
                float n = __shfl_up_sync(m, w, off);
                if (lane >= off) w += n;
            }
            if (lane < 16) s_a[lane] = w;
        }
        __syncthreads();

        float excl = ((wid > 0) ? s_a[wid - 1] : 0.0f) + (v - s0);
        g_coef[tid] = make_float4(excl, a0, b0, 0.0f);
        if (tid == TBL_N - 1)   // pad entry: valid for u == TBL_N exactly
            g_coef[TBL_N] = make_float4(excl + s0, hh * f0.y, 0.0f, 0.0f);
    }
    __syncthreads();
    if (tid == 0) g_cnt = 0;                 // reset for next graph replay
}

// -------------------------- kernel 2: pure map ------------------------------
#define S_THREADS 256
#define V4PT      (CHUNK / 4 / S_THREADS)  // 4 float4 per thread

__device__ __forceinline__ float evalG(float tv, float lo, float inv_h) {
    // u in [0, TBL_N] by construction (lo/hi are true min/max); pad entry
    // at TBL_N makes the unclamped index safe.
    float u = (tv - lo) * inv_h;
    int i = (int)u;
    float frac = u - (float)i;
    float4 c = __ldg(&g_coef[i]);
    return fmaf(frac, fmaf(frac, c.z, c.y), c.x);
}

__global__ __launch_bounds__(S_THREADS) void map_kernel(
    const float* __restrict__ t, float* __restrict__ out)
{
    int gid = blockIdx.x;
    int row = gid >> 2;                       // NCHUNK = 4
    size_t base = (size_t)row * N_SEQ + (size_t)(gid & 3) * CHUNK;

    float2 rg = g_range;
    float lo = rg.x, inv_h = rg.y;

    const float4* t4 = reinterpret_cast<const float4*>(t + base);
    float4* o4 = reinterpret_cast<float4*>(out + base);
    int tid = threadIdx.x;

    // issue ALL loads first (max MLP)
    float t0 = __ldg(&t[(size_t)row * N_SEQ]);     // row anchor
    float4 v[V4PT];
#pragma unroll
    for (int w = 0; w < V4PT; w++) v[w] = t4[tid + w * S_THREADS];

    float G0 = evalG(t0, lo, inv_h);
#pragma unroll
    for (int w = 0; w < V4PT; w++) {
        float4 o;
        o.x = evalG(v[w].x, lo, inv_h) - G0;
        o.y = evalG(v[w].y, lo, inv_h) - G0;
        o.z = evalG(v[w].z, lo, inv_h) - G0;
        o.w = evalG(v[w].w, lo, inv_h) - G0;
        o4[tid + w * S_THREADS] = o;
    }
}

// ----------------------------------------------------------------------------
extern "C" void kernel_launch(void* const* d_in, const int* in_sizes, int n_in,
                              void* d_out, int out_size) {
    const float* t  = (const float*)d_in[0];
    const float* W1 = (const float*)d_in[1];
    const float* b1 = (const float*)d_in[2];
    const float* W2 = (const float*)d_in[3];
    const float* b2 = (const float*)d_in[4];
    const float* W3 = (const float*)d_in[5];
    const float* b3 = (const float*)d_in[6];
    const float* W4 = (const float*)d_in[7];
    const float* b4 = (const float*)d_in[8];
    const float* W5 = (const float*)d_in[9];
    const float* b5 = (const float*)d_in[10];
    float* out = (float*)d_out;

    int total = in_sizes[0];          // B * N
    int nrows = total / N_SEQ;        // B

    table_kernel<<<NTB, 512>>>(t, nrows, W1, b1, W2, b2, W3, b3,
                               W4, b4, W5, b5, NTB);
    map_kernel<<<total / CHUNK, S_THREADS>>>(t, out);
}

// round 15
// speedup vs baseline: 1.2795x; 1.0015x over previous
#include <cuda_runtime.h>
#include <cstdint>
#include <math.h>

#define N_SEQ   16384
#define TBL_N   512                // intervals; TBL_N+1 knots
#define CHUNK   4096               // elements per map block
#define NTB     33                 // table blocks (16 knots each, 513 knots)

#define INP2 36                    // padded row widths (odd multiple of 16B)
#define INP3 68
#define INP4 68

// -------------------------- device scratch ---------------------------------
__device__ __align__(8)  float2 g_tbl2[TBL_N];      // (f[i], f[i+1]) pairs
__device__ __align__(16) float4 g_coef[TBL_N + 1];  // (G_i, a_i, b_i, 0) + pad
__device__ float2 g_range;                          // (c0 = -lo*inv_h, inv_h)
__device__ int    g_cnt;                            // table blocks done

// -------------------------- math helpers -----------------------------------
__device__ __forceinline__ float splus(float x) {
    float e = __expf(-fabsf(x));
    return fmaxf(x, 0.0f) + __logf(1.0f + e);
}

// ---------------- kernel 1: range + f at knots + prefix ---------------------
__global__ __launch_bounds__(512) void table_kernel(
    const float* __restrict__ t, int nrows,
    const float* __restrict__ W1, const float* __restrict__ b1,
    const float* __restrict__ W2, const float* __restrict__ b2,
    const float* __restrict__ W3, const float* __restrict__ b3,
    const float* __restrict__ W4, const float* __restrict__ b4,
    const float* __restrict__ W5, const float* __restrict__ b5,
    int nblk)
{
    // allow the dependent map kernel to launch immediately: its blocks
    // prefetch t (independent data) and block on cudaGridDependencySynchronize
    cudaTriggerProgrammaticLaunchCompletion();

    __shared__ __align__(16) float sW2p[64 * INP2];
    __shared__ __align__(16) float sW3p[64 * INP3];
    __shared__ __align__(16) float sW4p[32 * INP4];
    __shared__ __align__(16) float hbuf[16][2][64];   // [warp][pingpong][unit]
    __shared__ float sW1[32], sB1[32], sB2[64], sB3[64], sB4[32], sW5[32];
    __shared__ float sB5;
    __shared__ float s_a[16], s_b[16];
    __shared__ float s_lo, s_h;
    __shared__ int   s_last;

    int tid = threadIdx.x;
    int wid = tid >> 5, lane = tid & 31;
    const unsigned m = 0xffffffffu;

    // ---- stage weights (coalesced; padded rows -> conflict-free LDS.128)
    for (int d = tid; d < 2048; d += 512) {        // W2 [64][32]
        int j = d >> 5, k = d & 31;
        sW2p[j * INP2 + k] = W2[d];
    }
    for (int d = tid; d < 4096; d += 512) {        // W3 [64][64]
        int j = d >> 6, k = d & 63;
        sW3p[j * INP3 + k] = W3[d];
    }
    for (int d = tid; d < 2048; d += 512) {        // W4 [32][64]
        int j = d >> 6, k = d & 63;
        sW4p[j * INP4 + k] = W4[d];
    }
    if (tid < 32) { sW1[tid] = W1[tid]; sB1[tid] = b1[tid];
                    sB4[tid] = b4[tid]; sW5[tid] = W5[tid]; }
    if (tid < 64) { sB2[tid] = b2[tid]; sB3[tid] = b3[tid]; }
    if (tid == 0) sB5 = b5[0];

    // ---- per-block redundant edge range (t sorted per row)
    float l = 3.4e38f, h = -3.4e38f;
    for (int r = tid; r < nrows; r += 512) {
        l = fminf(l, __ldg(&t[(size_t)r * N_SEQ]));
        h = fmaxf(h, __ldg(&t[(size_t)r * N_SEQ + (N_SEQ - 1)]));
    }
#pragma unroll
    for (int off = 16; off > 0; off >>= 1) {
        l = fminf(l, __shfl_down_sync(m, l, off));
        h = fmaxf(h, __shfl_down_sync(m, h, off));
    }
    if (lane == 0) { s_a[wid] = l; s_b[wid] = h; }
    __syncthreads();
    if (tid == 0) {
        float lo = s_a[0], hi = s_b[0];
#pragma unroll
        for (int w = 1; w < 16; w++) {
            lo = fminf(lo, s_a[w]); hi = fmaxf(hi, s_b[w]);
        }
        float range = hi - lo;
        float hh    = (range > 1e-30f) ? range * (1.0f / TBL_N) : 1.0f;
        float inv_h = (range > 1e-30f) ? (float)TBL_N / range : 0.0f;
        s_lo = lo; s_h = hh;
        if (blockIdx.x == 0) g_range = make_float2(-lo * inv_h, inv_h);
    }
    __syncthreads();

    // ---- MLP: warp wid computes knot kn
    int kn = blockIdx.x * 16 + wid;
    if (kn <= TBL_N) {
        float tv = s_lo + (float)kn * s_h;

        // layer 1: 1 -> 32
        hbuf[wid][0][lane] = splus(fmaf(tv, sW1[lane], sB1[lane]));
        __syncwarp();
        // layer 2: 32 -> 64
        {
            const float4* hv4 = reinterpret_cast<const float4*>(hbuf[wid][0]);
            const float4* w0r = reinterpret_cast<const float4*>(sW2p + lane * INP2);
            const float4* w1r = reinterpret_cast<const float4*>(sW2p + (lane + 32) * INP2);
            float a0 = sB2[lane], a1 = sB2[lane + 32];
#pragma unroll
            for (int k4 = 0; k4 < 8; k4++) {
                float4 hv = hv4[k4];
                float4 w0 = w0r[k4];
                float4 w1 = w1r[k4];
                a0 = fmaf(w0.x, hv.x, a0); a0 = fmaf(w0.y, hv.y, a0);
                a0 = fmaf(w0.z, hv.z, a0); a0 = fmaf(w0.w, hv.w, a0);
                a1 = fmaf(w1.x, hv.x, a1); a1 = fmaf(w1.y, hv.y, a1);
                a1 = fmaf(w1.z, hv.z, a1); a1 = fmaf(w1.w, hv.w, a1);
            }
            hbuf[wid][1][lane]      = splus(a0);
            hbuf[wid][1][lane + 32] = splus(a1);
        }
        __syncwarp();
        // layer 3: 64 -> 64
        {
            const float4* hv4 = reinterpret_cast<const float4*>(hbuf[wid][1]);
            const float4* w0r = reinterpret_cast<const float4*>(sW3p + lane * INP3);
            const float4* w1r = reinterpret_cast<const float4*>(sW3p + (lane + 32) * INP3);
            float a0 = sB3[lane], a1 = sB3[lane + 32];
#pragma unroll
            for (int k4 = 0; k4 < 16; k4++) {
                float4 hv = hv4[k4];
                float4 w0 = w0r[k4];
                float4 w1 = w1r[k4];
                a0 = fmaf(w0.x, hv.x, a0); a0 = fmaf(w0.y, hv.y, a0);
                a0 = fmaf(w0.z, hv.z, a0); a0 = fmaf(w0.w, hv.w, a0);
                a1 = fmaf(w1.x, hv.x, a1); a1 = fmaf(w1.y, hv.y, a1);
                a1 = fmaf(w1.z, hv.z, a1); a1 = fmaf(w1.w, hv.w, a1);
            }
            hbuf[wid][0][lane]      = splus(a0);
            hbuf[wid][0][lane + 32] = splus(a1);
        }
        __syncwarp();
        // layer 4: 64 -> 32
        float h4;
        {
            const float4* hv4 = reinterpret_cast<const float4*>(hbuf[wid][0]);
            const float4* w0r = reinterpret_cast<const float4*>(sW4p + lane * INP4);
            float a0 = sB4[lane];
#pragma unroll
            for (int k4 = 0; k4 < 16; k4++) {
                float4 hv = hv4[k4];
                float4 w0 = w0r[k4];
                a0 = fmaf(w0.x, hv.x, a0); a0 = fmaf(w0.y, hv.y, a0);
                a0 = fmaf(w0.z, hv.z, a0); a0 = fmaf(w0.w, hv.w, a0);
            }
            h4 = splus(a0);
        }
        // layer 5: 32 -> 1 (warp reduce)
        float p = h4 * sW5[lane];
#pragma unroll
        for (int off = 16; off > 0; off >>= 1)
            p += __shfl_xor_sync(m, p, off);

        if (lane == 0) {
            float v = splus(p + sB5) + 1.0f;
            float* tbl = reinterpret_cast<float*>(g_tbl2);
            if (kn < TBL_N) tbl[2 * kn] = v;
            if (kn >= 1)    tbl[2 * (kn - 1) + 1] = v;
            __threadfence();                 // publish before the counter
        }
    }
    __syncthreads();

    // ---- last block computes antiderivative coefficients -------------------
    if (tid == 0) {
        int old = atomicAdd(&g_cnt, 1);
        s_last = (old == nblk - 1);
    }
    __syncthreads();
    if (!s_last) return;

    {
        float hh = s_h;
        // one interval per thread (TBL_N = 512)
        float2 f0 = __ldcg(&g_tbl2[tid]);
        float a0 = hh * f0.x, b0 = 0.5f * hh * (f0.y - f0.x);
        float s0 = a0 + b0;

        float v = s0;
#pragma unroll
        for (int off = 1; off < 32; off <<= 1) {
            float n = __shfl_up_sync(m, v, off);
            if (lane >= off) v += n;
        }
        if (lane == 31) s_a[wid] = v;
        __syncthreads();
        if (wid == 0) {
            float w = (lane < 16) ? s_a[lane] : 0.0f;
#pragma unroll
            for (int off = 1; off < 16; off <<= 1) {
                float n = __shfl_up_sync(m, w, off);
                if (lane >= off) w += n;
            }
            if (lane < 16) s_a[lane] = w;
        }
        __syncthreads();

        float excl = ((wid > 0) ? s_a[wid - 1] : 0.0f) + (v - s0);
        g_coef[tid] = make_float4(excl, a0, b0, 0.0f);
        if (tid == TBL_N - 1)   // pad entry: valid for u == TBL_N exactly
            g_coef[TBL_N] = make_float4(excl + s0, hh * f0.y, 0.0f, 0.0f);
    }
    __syncthreads();
    if (tid == 0) g_cnt = 0;                 // reset for next graph replay
}

// -------------------------- kernel 2: map (PDL secondary) -------------------
#define S_THREADS 512
#define V4PT      (CHUNK / 4 / S_THREADS)  // 2 float4 per thread

__device__ __forceinline__ float evalG(float tv, float c0, float inv_h) {
    // u in [0, TBL_N + eps); pad entry at TBL_N keeps unclamped index safe.
    float u = fmaf(tv, inv_h, c0);
    int i = (int)u;
    float frac = u - (float)i;
    float4 c = __ldg(&g_coef[i]);
    return fmaf(frac, fmaf(frac, c.z, c.y), c.x);
}

__global__ __launch_bounds__(S_THREADS) void map_kernel(
    const float* __restrict__ t, float* __restrict__ out)
{
    int gid = blockIdx.x;
    int row = gid >> 2;                       // NCHUNK = 4
    size_t base = (size_t)row * N_SEQ + (size_t)(gid & 3) * CHUNK;
    int tid = threadIdx.x;

    // ---- prefetch everything that does NOT depend on the table -------------
    const float4* t4 = reinterpret_cast<const float4*>(t + base);
    float t0 = __ldg(&t[(size_t)row * N_SEQ]);     // row anchor
    float4 v0 = t4[tid];
    float4 v1 = t4[tid + S_THREADS];

    // ---- wait for table_kernel completion (PDL) -----------------------------
    cudaGridDependencySynchronize();

    float2 rg = g_range;
    float c0 = rg.x, inv_h = rg.y;
    float G0 = evalG(t0, c0, inv_h);

    float4* o4 = reinterpret_cast<float4*>(out + base);
    float4 o;
    o.x = evalG(v0.x, c0, inv_h) - G0;
    o.y = evalG(v0.y, c0, inv_h) - G0;
    o.z = evalG(v0.z, c0, inv_h) - G0;
    o.w = evalG(v0.w, c0, inv_h) - G0;
    o4[tid] = o;
    o.x = evalG(v1.x, c0, inv_h) - G0;
    o.y = evalG(v1.y, c0, inv_h) - G0;
    o.z = evalG(v1.z, c0, inv_h) - G0;
    o.w = evalG(v1.w, c0, inv_h) - G0;
    o4[tid + S_THREADS] = o;
}

// ----------------------------------------------------------------------------
extern "C" void kernel_launch(void* const* d_in, const int* in_sizes, int n_in,
                              void* d_out, int out_size) {
    const float* t  = (const float*)d_in[0];
    const float* W1 = (const float*)d_in[1];
    const float* b1 = (const float*)d_in[2];
    const float* W2 = (const float*)d_in[3];
    const float* b2 = (const float*)d_in[4];
    const float* W3 = (const float*)d_in[5];
    const float* b3 = (const float*)d_in[6];
    const float* W4 = (const float*)d_in[7];
    const float* b4 = (const float*)d_in[8];
    const float* W5 = (const float*)d_in[9];
    const float* b5 = (const float*)d_in[10];
    float* out = (float*)d_out;

    int total = in_sizes[0];          // B * N
    int nrows = total / N_SEQ;        // B

    table_kernel<<<NTB, 512>>>(t, nrows, W1, b1, W2, b2, W3, b3,
                               W4, b4, W5, b5, NTB);

    // map: programmatic dependent launch — overlaps its t prefetch with table
    cudaLaunchConfig_t cfg = {};
    cfg.gridDim  = dim3((unsigned)(total / CHUNK), 1, 1);
    cfg.blockDim = dim3(S_THREADS, 1, 1);
    cudaLaunchAttribute attrs[1];
    attrs[0].id = cudaLaunchAttributeProgrammaticStreamSerialization;
    attrs[0].val.programmaticStreamSerializationAllowed = 1;
    cfg.attrs = attrs;
    cfg.numAttrs = 1;
    cudaLaunchKernelEx(&cfg, map_kernel, t, out);
}

// round 16
// speedup vs baseline: 1.4654x; 1.1453x over previous
#include <cuda_runtime.h>
#include <cstdint>
#include <math.h>

#define N_SEQ   16384
#define TBL_N   256                // intervals; TBL_N+1 knots
#define CHUNK   4096               // elements per map block
#define NTB     17                 // table blocks (16 knots each, 257 knots)

#define INP2 36                    // padded row widths (odd multiple of 16B)
#define INP3 68
#define INP4 68

// -------------------------- device scratch ---------------------------------
__device__ __align__(8)  float2 g_tbl2[TBL_N];      // (f[i], f[i+1]) pairs
__device__ __align__(16) float4 g_coef[TBL_N + 1];  // (G_i, a_i, b_i, 0) + pad
__device__ float2 g_range;                          // (c0 = -lo*inv_h, inv_h)
__device__ int    g_cnt;                            // table blocks done

// -------------------------- math helpers -----------------------------------
__device__ __forceinline__ float splus(float x) {
    float e = __expf(-fabsf(x));
    return fmaxf(x, 0.0f) + __logf(1.0f + e);
}

// ---------------- kernel 1: range + f at knots + prefix ---------------------
__global__ __launch_bounds__(512) void table_kernel(
    const float* __restrict__ t, int nrows,
    const float* __restrict__ W1, const float* __restrict__ b1,
    const float* __restrict__ W2, const float* __restrict__ b2,
    const float* __restrict__ W3, const float* __restrict__ b3,
    const float* __restrict__ W4, const float* __restrict__ b4,
    const float* __restrict__ W5, const float* __restrict__ b5,
    int nblk)
{
    // let the dependent map kernel launch early (it prefetches t, then waits)
    cudaTriggerProgrammaticLaunchCompletion();

    __shared__ __align__(16) float sW2p[64 * INP2];
    __shared__ __align__(16) float sW3p[64 * INP3];
    __shared__ __align__(16) float sW4p[32 * INP4];
    __shared__ __align__(16) float hbuf[16][2][64];   // [warp][pingpong][unit]
    __shared__ float sW1[32], sB1[32], sB2[64], sB3[64], sB4[32], sW5[32];
    __shared__ float sB5;
    __shared__ float s_a[16], s_b[16];
    __shared__ float s_lo, s_h;
    __shared__ int   s_last;

    int tid = threadIdx.x;
    int wid = tid >> 5, lane = tid & 31;
    const unsigned m = 0xffffffffu;

    // ---- stage weights (coalesced; padded rows -> conflict-free LDS.128)
    for (int d = tid; d < 2048; d += 512) {        // W2 [64][32]
        int j = d >> 5, k = d & 31;
        sW2p[j * INP2 + k] = W2[d];
    }
    for (int d = tid; d < 4096; d += 512) {        // W3 [64][64]
        int j = d >> 6, k = d & 63;
        sW3p[j * INP3 + k] = W3[d];
    }
    for (int d = tid; d < 2048; d += 512) {        // W4 [32][64]
        int j = d >> 6, k = d & 63;
        sW4p[j * INP4 + k] = W4[d];
    }
    if (tid < 32) { sW1[tid] = W1[tid]; sB1[tid] = b1[tid];
                    sB4[tid] = b4[tid]; sW5[tid] = W5[tid]; }
    if (tid < 64) { sB2[tid] = b2[tid]; sB3[tid] = b3[tid]; }
    if (tid == 0) sB5 = b5[0];

    // ---- per-block redundant edge range (t sorted per row)
    float l = 3.4e38f, h = -3.4e38f;
    for (int r = tid; r < nrows; r += 512) {
        l = fminf(l, __ldg(&t[(size_t)r * N_SEQ]));
        h = fmaxf(h, __ldg(&t[(size_t)r * N_SEQ + (N_SEQ - 1)]));
    }
#pragma unroll
    for (int off = 16; off > 0; off >>= 1) {
        l = fminf(l, __shfl_down_sync(m, l, off));
        h = fmaxf(h, __shfl_down_sync(m, h, off));
    }
    if (lane == 0) { s_a[wid] = l; s_b[wid] = h; }
    __syncthreads();
    if (tid == 0) {
        float lo = s_a[0], hi = s_b[0];
#pragma unroll
        for (int w = 1; w < 16; w++) {
            lo = fminf(lo, s_a[w]); hi = fmaxf(hi, s_b[w]);
        }
        float range = hi - lo;
        float hh    = (range > 1e-30f) ? range * (1.0f / TBL_N) : 1.0f;
        float inv_h = (range > 1e-30f) ? (float)TBL_N / range : 0.0f;
        s_lo = lo; s_h = hh;
        if (blockIdx.x == 0) g_range = make_float2(-lo * inv_h, inv_h);
    }
    __syncthreads();

    // ---- MLP: warp wid computes knot kn
    int kn = blockIdx.x * 16 + wid;
    if (kn <= TBL_N) {
        float tv = s_lo + (float)kn * s_h;

        // layer 1: 1 -> 32
        hbuf[wid][0][lane] = splus(fmaf(tv, sW1[lane], sB1[lane]));
        __syncwarp();
        // layer 2: 32 -> 64
        {
            const float4* hv4 = reinterpret_cast<const float4*>(hbuf[wid][0]);
            const float4* w0r = reinterpret_cast<const float4*>(sW2p + lane * INP2);
            const float4* w1r = reinterpret_cast<const float4*>(sW2p + (lane + 32) * INP2);
            float a0 = sB2[lane], a1 = sB2[lane + 32];
#pragma unroll
            for (int k4 = 0; k4 < 8; k4++) {
                float4 hv = hv4[k4];
                float4 w0 = w0r[k4];
                float4 w1 = w1r[k4];
                a0 = fmaf(w0.x, hv.x, a0); a0 = fmaf(w0.y, hv.y, a0);
                a0 = fmaf(w0.z, hv.z, a0); a0 = fmaf(w0.w, hv.w, a0);
                a1 = fmaf(w1.x, hv.x, a1); a1 = fmaf(w1.y, hv.y, a1);
                a1 = fmaf(w1.z, hv.z, a1); a1 = fmaf(w1.w, hv.w, a1);
            }
            hbuf[wid][1][lane]      = splus(a0);
            hbuf[wid][1][lane + 32] = splus(a1);
        }
        __syncwarp();
        // layer 3: 64 -> 64
        {
            const float4* hv4 = reinterpret_cast<const float4*>(hbuf[wid][1]);
            const float4* w0r = reinterpret_cast<const float4*>(sW3p + lane * INP3);
            const float4* w1r = reinterpret_cast<const float4*>(sW3p + (lane + 32) * INP3);
            float a0 = sB3[lane], a1 = sB3[lane + 32];
#pragma unroll
            for (int k4 = 0; k4 < 16; k4++) {
                float4 hv = hv4[k4];
                float4 w0 = w0r[k4];
                float4 w1 = w1r[k4];
                a0 = fmaf(w0.x, hv.x, a0); a0 = fmaf(w0.y, hv.y, a0);
                a0 = fmaf(w0.z, hv.z, a0); a0 = fmaf(w0.w, hv.w, a0);
                a1 = fmaf(w1.x, hv.x, a1); a1 = fmaf(w1.y, hv.y, a1);
                a1 = fmaf(w1.z, hv.z, a1); a1 = fmaf(w1.w, hv.w, a1);
            }
            hbuf[wid][0][lane]      = splus(a0);
            hbuf[wid][0][lane + 32] = splus(a1);
        }
        __syncwarp();
        // layer 4: 64 -> 32
        float h4;
        {
            const float4* hv4 = reinterpret_cast<const float4*>(hbuf[wid][0]);
            const float4* w0r = reinterpret_cast<const float4*>(sW4p + lane * INP4);
            float a0 = sB4[lane];
#pragma unroll
            for (int k4 = 0; k4 < 16; k4++) {
                float4 hv = hv4[k4];
                float4 w0 = w0r[k4];
                a0 = fmaf(w0.x, hv.x, a0); a0 = fmaf(w0.y, hv.y, a0);
                a0 = fmaf(w0.z, hv.z, a0); a0 = fmaf(w0.w, hv.w, a0);
            }
            h4 = splus(a0);
        }
        // layer 5: 32 -> 1 (warp reduce)
        float p = h4 * sW5[lane];
#pragma unroll
        for (int off = 16; off > 0; off >>= 1)
            p += __shfl_xor_sync(m, p, off);

        if (lane == 0) {
            float v = splus(p + sB5) + 1.0f;
            float* tbl = reinterpret_cast<float*>(g_tbl2);
            if (kn < TBL_N) tbl[2 * kn] = v;
            if (kn >= 1)    tbl[2 * (kn - 1) + 1] = v;
            __threadfence();                 // publish before the counter
        }
    }
    __syncthreads();

    // ---- last block computes antiderivative coefficients -------------------
    if (tid == 0) {
        int old = atomicAdd(&g_cnt, 1);
        s_last = (old == nblk - 1);
    }
    __syncthreads();
    if (!s_last) return;

    {
        float hh = s_h;
        // one interval per thread for tid < TBL_N; others carry 0 in the scan
        float a0 = 0.0f, b0 = 0.0f, s0 = 0.0f;
        float fy = 0.0f;
        if (tid < TBL_N) {
            float2 f0 = __ldcg(&g_tbl2[tid]);
            a0 = hh * f0.x; b0 = 0.5f * hh * (f0.y - f0.x);
            s0 = a0 + b0;
            fy = f0.y;
        }

        float v = s0;
#pragma unroll
        for (int off = 1; off < 32; off <<= 1) {
            float n = __shfl_up_sync(m, v, off);
            if (lane >= off) v += n;
        }
        if (lane == 31) s_a[wid] = v;
        __syncthreads();
        if (wid == 0) {
            float w = (lane < 16) ? s_a[lane] : 0.0f;
#pragma unroll
            for (int off = 1; off < 16; off <<= 1) {
                float n = __shfl_up_sync(m, w, off);
                if (lane >= off) w += n;
            }
            if (lane < 16) s_a[lane] = w;
        }
        __syncthreads();

        float excl = ((wid > 0) ? s_a[wid - 1] : 0.0f) + (v - s0);
        if (tid < TBL_N) {
            g_coef[tid] = make_float4(excl, a0, b0, 0.0f);
            if (tid == TBL_N - 1)   // pad entry: valid for u == TBL_N exactly
                g_coef[TBL_N] = make_float4(excl + s0, hh * fy, 0.0f, 0.0f);
        }
    }
    __syncthreads();
    if (tid == 0) g_cnt = 0;                 // reset for next graph replay
}

// -------------------------- kernel 2: map (PDL secondary) -------------------
#define S_THREADS 512

__device__ __forceinline__ float evalGs(float tv, float c0, float inv_h,
                                        const float4* __restrict__ scoef) {
    // u in [0, TBL_N + eps); pad entry at TBL_N keeps unclamped index safe.
    float u = fmaf(tv, inv_h, c0);
    int i = (int)u;
    float frac = u - (float)i;
    float4 c = scoef[i];                    // LDS.128, broadcast-friendly
    return fmaf(frac, fmaf(frac, c.z, c.y), c.x);
}

__global__ __launch_bounds__(S_THREADS) void map_kernel(
    const float* __restrict__ t, float* __restrict__ out)
{
    __shared__ __align__(16) float4 scoef[TBL_N + 1];   // 4.1 KB

    int gid = blockIdx.x;
    int row = gid >> 2;                       // NCHUNK = 4
    size_t base = (size_t)row * N_SEQ + (size_t)(gid & 3) * CHUNK;
    int tid = threadIdx.x;

    // ---- prefetch everything that does NOT depend on the table -------------
    const float4* t4 = reinterpret_cast<const float4*>(t + base);
    float t0 = __ldg(&t[(size_t)row * N_SEQ]);     // row anchor
    float4 v0 = t4[tid];
    float4 v1 = t4[tid + S_THREADS];

    // ---- wait for table_kernel completion (PDL) -----------------------------
    cudaGridDependencySynchronize();

    // ---- stage coefficient table into shared memory -------------------------
    if (tid <= TBL_N) scoef[tid] = g_coef[tid];
    float2 rg = g_range;
    __syncthreads();

    float c0 = rg.x, inv_h = rg.y;
    float G0 = evalGs(t0, c0, inv_h, scoef);

    float4* o4 = reinterpret_cast<float4*>(out + base);
    float4 o;
    o.x = evalGs(v0.x, c0, inv_h, scoef) - G0;
    o.y = evalGs(v0.y, c0, inv_h, scoef) - G0;
    o.z = evalGs(v0.z, c0, inv_h, scoef) - G0;
    o.w = evalGs(v0.w, c0, inv_h, scoef) - G0;
    o4[tid] = o;
    o.x = evalGs(v1.x, c0, inv_h, scoef) - G0;
    o.y = evalGs(v1.y, c0, inv_h, scoef) - G0;
    o.z = evalGs(v1.z, c0, inv_h, scoef) - G0;
    o.w = evalGs(v1.w, c0, inv_h, scoef) - G0;
    o4[tid + S_THREADS] = o;
}

// ----------------------------------------------------------------------------
extern "C" void kernel_launch(void* const* d_in, const int* in_sizes, int n_in,
                              void* d_out, int out_size) {
    const float* t  = (const float*)d_in[0];
    const float* W1 = (const float*)d_in[1];
    const float* b1 = (const float*)d_in[2];
    const float* W2 = (const float*)d_in[3];
    const float* b2 = (const float*)d_in[4];
    const float* W3 = (const float*)d_in[5];
    const float* b3 = (const float*)d_in[6];
    const float* W4 = (const float*)d_in[7];
    const float* b4 = (const float*)d_in[8];
    const float* W5 = (const float*)d_in[9];
    const float* b5 = (const float*)d_in[10];
    float* out = (float*)d_out;

    int total = in_sizes[0];          // B * N
    int nrows = total / N_SEQ;        // B

    table_kernel<<<NTB, 512>>>(t, nrows, W1, b1, W2, b2, W3, b3,
                               W4, b4, W5, b5, NTB);

    // map: programmatic dependent launch — overlaps its t prefetch with table
    cudaLaunchConfig_t cfg = {};
    cfg.gridDim  = dim3((unsigned)(total / CHUNK), 1, 1);
    cfg.blockDim = dim3(S_THREADS, 1, 1);
    cudaLaunchAttribute attrs[1];
    attrs[0].id = cudaLaunchAttributeProgrammaticStreamSerialization;
    attrs[0].val.programmaticStreamSerializationAllowed = 1;
    cfg.attrs = attrs;
    cfg.numAttrs = 1;
    cudaLaunchKernelEx(&cfg, map_kernel, t, out);
}